// round 14
// baseline (speedup 1.0000x reference)
#include <cuda_runtime.h>
#include <cstddef>

#define Mn   2048
#define LLn  64
#define Pp   4
#define Ssn  2
#define RPB  16
#define NTHR 544              /* 16 consumer warps + 1 producer warp */
#define NCONS 512
#define NBLK (Mn/RPB)
#define NBUF 6
#define TILE_FLOATS 8192      /* 16 k x 512 cols x f32 = 32KB */
#define TILE_BYTES  32768

// smem floats: ring 6*8192 | hA ping-pong 2*2048 | ids 96 | mbarriers (12 x 8B)
#define OFF_HA   49152
#define HA_STRIDE 2048
#define OFF_ID   (OFF_HA + 2*HA_STRIDE)     /* 53248 */
#define OFF_BAR  (OFF_ID + 96)              /* 53344 */
#define SMEMB    (OFF_BAR*4 + 96)           /* 213472 B */

__device__ __align__(256) float g_EWm[(size_t)LLn * Mn * 512];
__device__ __align__(256) float g_EWs[(size_t)LLn * Mn * 512];
__device__ float g_c0[128];
__device__ float g_z1b[512];
// k-pair packed: [kp(64)][col(512)] float2 = {W[2kp][col], W[2kp+1][col]}
__device__ __align__(256) float g_Ump[65536];
__device__ __align__(256) float g_Usp[65536];
__device__ __align__(256) float g_Wmp[65536];
__device__ __align__(256) float g_Wsp[65536];

typedef unsigned long long u64t;

__device__ __forceinline__ float2 u2f(u64t u){ float2 v; asm("mov.b64 {%0,%1},%2;":"=f"(v.x),"=f"(v.y):"l"(u)); return v; }
__device__ __forceinline__ void fma2(u64t&a, u64t x, u64t w){ asm("fma.rn.f32x2 %0,%1,%2,%0;":"+l"(a):"l"(x),"l"(w)); }
__device__ __forceinline__ float redu(u64t a){ float2 v=u2f(a); return v.x+v.y; }

__device__ __forceinline__ unsigned smu32(const void* p){
  unsigned a; asm("{ .reg .u64 t; cvta.to.shared.u64 t, %1; cvt.u32.u64 %0, t; }":"=r"(a):"l"(p)); return a;
}
__device__ __forceinline__ void mb_init(unsigned mb, unsigned cnt){
  asm volatile("mbarrier.init.shared.b64 [%0], %1;"::"r"(mb),"r"(cnt):"memory");
}
__device__ __forceinline__ void mb_wait(unsigned mb, int ph){
  asm volatile("{\n\t.reg .pred P;\n\tWL%=:\n\tmbarrier.try_wait.parity.acquire.cta.shared::cta.b64 P, [%0], %1, 0x989680;\n\t@P bra WD%=;\n\tbra WL%=;\n\tWD%=:\n\t}"
    ::"r"(mb),"r"(ph):"memory");
}
__device__ __forceinline__ void mb_arrive(unsigned mb){
  asm volatile("mbarrier.arrive.shared.b64 _, [%0];"::"r"(mb):"memory");
}
__device__ __forceinline__ void mb_expect_tx(unsigned mb, unsigned bytes){
  asm volatile("mbarrier.arrive.expect_tx.shared.b64 _, [%0], %1;"::"r"(mb),"r"(bytes):"memory");
}
__device__ __forceinline__ void bulk_cp(unsigned dst, const float* src, unsigned bytes, unsigned mb){
  asm volatile("cp.async.bulk.shared::cta.global.mbarrier::complete_tx::bytes [%0], [%1], %2, [%3];"
    ::"r"(dst),"l"(src),"r"(bytes),"r"(mb):"memory");
}
#define CBAR()  asm volatile("bar.sync 1, %0;"::"n"(NCONS):"memory")
#define TBAR(t) asm volatile("bar.sync %0, 128;"::"r"(2+(t)):"memory")

__device__ __forceinline__ float sigf(float x){ return 1.f/(1.f+__expf(-x)); }
__device__ __forceinline__ float tfast(float x){
  x = fminf(fmaxf(x,-15.f),15.f);
  float t = __expf(2.f*x);
  return (t-1.f)/(t+1.f);
}

// ---------------- producer: stream npass*8 tiles through the 6-ring ----------------
__device__ __forceinline__ void producer(unsigned barb, unsigned smbase,
    const float* const* sched, int npass)
{
  int i=0;
  #pragma unroll 1
  for(int p=0;p<npass;p++){
    const float* W = sched[p];
    #pragma unroll 1
    for(int t=0;t<8;t++,i++){
      int s = i % NBUF;
      unsigned fb = barb + s*16;       // full barrier
      if(i >= NBUF) mb_wait(fb + 8, ((i-NBUF)/NBUF)&1);   // empty barrier
      mb_expect_tx(fb, TILE_BYTES);
      bulk_cp(smbase + s*TILE_BYTES, W + t*TILE_FLOATS, TILE_BYTES, fb);
    }
  }
}

// ---------------- consumer: one 512-col GEMM pass over 8 pipelined tiles -----------
// Thread layout: 16 warps = 4 teams x 4 warps; team=wid>>2 owns rows tr0=4*team..+3.
// Warp wsub=wid&3 covers dims [32*wsub,+32); lane cg owns dim d0=32*wsub+cg.
// Thread's 4 z-cols: gate g -> col 128*g+d0. acc[r][g]: u64 {k-even, k-odd} sums.
// NOTE: gemm reads ONLY its own team's hA rows -> intra-layer sync is per-team.
__device__ __forceinline__ void gemm_pipe(u64t acc[4][4], const float* xs,
    const float* bufbase, unsigned barb, int d0, int tr0, int cg, int& tc)
{
  #pragma unroll 1
  for(int t=0;t<8;t++){
    int s = tc % NBUF;
    unsigned fb = barb + s*16;
    mb_wait(fb, (tc/NBUF)&1);
    const u64t* wb = (const u64t*)(bufbase + s*TILE_FLOATS);
    const float* xb = xs + 16*t;
    #pragma unroll
    for(int kq=0;kq<4;kq++){
      const u64t* wA = wb + (2*kq  )*512 + d0;
      const u64t* wB = wb + (2*kq+1)*512 + d0;
      u64t a0=wA[0], a1=wA[128], a2=wA[256], a3=wA[384];
      u64t b0=wB[0], b1=wB[128], b2=wB[256], b3=wB[384];
      #pragma unroll
      for(int r=0;r<4;r++){
        ulonglong2 xv = *(const ulonglong2*)(xb + (tr0+r)*128 + 4*kq);
        fma2(acc[r][0], xv.x, a0); fma2(acc[r][1], xv.x, a1);
        fma2(acc[r][2], xv.x, a2); fma2(acc[r][3], xv.x, a3);
        fma2(acc[r][0], xv.y, b0); fma2(acc[r][1], xv.y, b1);
        fma2(acc[r][2], xv.y, b2); fma2(acc[r][3], xv.y, b3);
      }
    }
    __syncwarp();
    if(cg==0) mb_arrive(fb + 8);
    tc++;
  }
}

__device__ __forceinline__ void zero_acc(u64t acc[4][4]){
  #pragma unroll
  for(int r=0;r<4;r++)
    #pragma unroll
    for(int g=0;g<4;g++) acc[r][g]=0ull;
}

// z: i,f,g,o scalars for this thread's dim; updates c, returns h.
__device__ __forceinline__ float cell1(const float z[4], float& c){
  c = sigf(z[1])*c + sigf(z[0])*tfast(z[2]);
  return sigf(z[3])*tfast(c);
}

// prefetch one table row set: ep[r][g] = tab[id[r]][128g+d0]
__device__ __forceinline__ void pref4(float ep[4][4], const float* tab,
    const int* ids, int stride, int off, int tr0, int d0)
{
  #pragma unroll
  for(int r=0;r<4;r++){
    const float* e = tab + (size_t)ids[off + (tr0+r)*stride]*512;
    #pragma unroll
    for(int g=0;g<4;g++) ep[r][g] = __ldg(e + 128*g + d0);
  }
}

__global__ void __launch_bounds__(NTHR,1) layer_kernel(int l, float* __restrict__ emb,
  const int* __restrict__ prop, const int* __restrict__ sup,
  const float* __restrict__ bm, const float* __restrict__ bs)
{
  extern __shared__ float smx[];
  float* hA0 = smx + OFF_HA;
  float* hA1 = smx + OFF_HA + HA_STRIDE;
  int*  ids  = (int*)(smx + OFF_ID);
  const int tid=threadIdx.x, cg=tid&31, wid=tid>>5;
  const unsigned smbase = smu32(smx);
  const unsigned barb   = smbase + OFF_BAR*4;
  const int lrow0 = blockIdx.x*RPB;
  const int base  = l*Mn + lrow0;

  if(tid==0){
    #pragma unroll
    for(int s=0;s<NBUF;s++){ mb_init(barb+s*16, 1); mb_init(barb+s*16+8, 16); }
  }
  if(tid<RPB*Pp) ids[tid] = prop[lrow0*Pp + tid];
  else if(tid<RPB*Pp+RPB*Ssn) ids[tid] = sup[lrow0*Ssn + (tid-RPB*Pp)];
  __syncthreads();

  if(wid==16){
    if(cg==0){
      const float* sched[8]={g_Ump,g_Ump,g_Ump,g_Wsp,g_Usp,g_Usp,g_Wmp,g_Wsp};
      producer(barb, smbase, sched, 8);
    }
    return;
  }

  const int team=wid>>2, wsub=wid&3;
  const int d0  = 32*wsub + cg;
  const int tr0 = 4*team;
  int tc = 0;

  u64t acc[4][4];
  float zl[4][4], zz[4][4], ep[4][4];
  float cst[4], z[4];
  float bmv[4], bsv[4];
  #pragma unroll
  for(int g=0;g<4;g++){ bmv[g]=__ldg(bm+128*g+d0); bsv[g]=__ldg(bs+128*g+d0); }

  // ---- member t=1: z = E_Wm[pid0] + z1b ; c_prev = c0  (cell -> hA0)
  {
    float c0v = g_c0[d0];
    #pragma unroll
    for(int r=0;r<4;r++){
      const float* e = g_EWm + (size_t)ids[(tr0+r)*Pp]*512;
      #pragma unroll
      for(int g=0;g<4;g++) z[g] = e[128*g+d0] + g_z1b[128*g+d0];
      cst[r]=c0v;
      hA0[(tr0+r)*128 + d0] = cell1(z, cst[r]);
    }
  }
  TBAR(team);

  // ---- member t=2..4: z = E_Wm[pid_{t-1}] + h @ Um ; ping-pong hA
  // t=2: read hA0 -> write hA1 ; t=3: read hA1 -> write hA0 ; t=4: read hA0 -> write hA1
  #pragma unroll 1
  for(int t=2;t<=4;t++){
    const float* rb = (t&1) ? hA1 : hA0;   // t=2:hA0, t=3:hA1, t=4:hA0
    float*       wbv= (t&1) ? hA0 : hA1;
    pref4(ep, g_EWm, ids, Pp, t-1, tr0, d0);      // prefetch gathers before gemm
    zero_acc(acc);
    gemm_pipe(acc, rb, smx, barb, d0, tr0, cg, tc);
    #pragma unroll
    for(int r=0;r<4;r++){
      #pragma unroll
      for(int g=0;g<4;g++) zz[r][g] = redu(acc[r][g]) + ep[r][g];
      wbv[(tr0+r)*128 + d0] = cell1(zz[r], cst[r]);
    }
    TBAR(team);                   // team's new h visible (no WAR: different buffer)
  }
  // hA1 == h_m

  // ---- zl = b_s + h_m @ Ws  (x-contribution of super t=2, kept in regs)
  pref4(ep, g_EWs, ids, Ssn, RPB*Pp + 0, tr0, d0);   // prefetch super-t0 gathers
  zero_acc(acc);
  gemm_pipe(acc, hA1, smx, barb, d0, tr0, cg, tc);
  #pragma unroll
  for(int r=0;r<4;r++)
    #pragma unroll
    for(int g=0;g<4;g++) zl[r][g] = redu(acc[r][g]) + bsv[g];

  // ---- super t=0: z = E_Ws[sid0], zero state  (write hA0; hA0's last readers
  //      finished before the TBAR after t=4; zl gemm read hA1 -> no hazard)
  #pragma unroll
  for(int r=0;r<4;r++){
    #pragma unroll
    for(int g=0;g<4;g++) z[g] = ep[r][g];
    cst[r]=0.f;
    hA0[(tr0+r)*128 + d0] = cell1(z, cst[r]);
  }
  TBAR(team);

  // ---- super t=1: z = E_Ws[sid1] + h @ Us  (read hA0 -> write hA1)
  pref4(ep, g_EWs, ids, Ssn, RPB*Pp + 1, tr0, d0);
  zero_acc(acc);
  gemm_pipe(acc, hA0, smx, barb, d0, tr0, cg, tc);
  #pragma unroll
  for(int r=0;r<4;r++){
    #pragma unroll
    for(int g=0;g<4;g++) zz[r][g] = redu(acc[r][g]) + ep[r][g];
    hA1[(tr0+r)*128 + d0] = cell1(zz[r], cst[r]);
  }
  TBAR(team);

  // ---- super t=2: z = zl + h @ Us -> h_s  (read hA1 -> write hA0)
  zero_acc(acc);
  gemm_pipe(acc, hA1, smx, barb, d0, tr0, cg, tc);
  #pragma unroll
  for(int r=0;r<4;r++){
    #pragma unroll
    for(int g=0;g<4;g++) zz[r][g] = redu(acc[r][g]) + zl[r][g];
    hA0[(tr0+r)*128 + d0] = cell1(zz[r], cst[r]);
  }

  // ---- write emb rows (cross-team read of hA0 -> one full consumer barrier)
  CBAR();
  ((float4*)(emb + (size_t)base*128))[tid] = ((const float4*)hA0)[tid];

  // ---- produce z-tables for this layer's rows (gemm reads own-team hA0 rows only)
  zero_acc(acc);
  gemm_pipe(acc, hA0, smx, barb, d0, tr0, cg, tc);
  #pragma unroll
  for(int r=0;r<4;r++){
    float* dr = g_EWm + (size_t)(base+tr0+r)*512;
    #pragma unroll
    for(int g=0;g<4;g++) dr[128*g+d0] = redu(acc[r][g]) + bmv[g];
  }
  zero_acc(acc);
  gemm_pipe(acc, hA0, smx, barb, d0, tr0, cg, tc);
  #pragma unroll
  for(int r=0;r<4;r++){
    float* dr = g_EWs + (size_t)(base+tr0+r)*512;
    #pragma unroll
    for(int g=0;g<4;g++) dr[128*g+d0] = redu(acc[r][g]) + bsv[g];
  }
}

__global__ void __launch_bounds__(NTHR,1) layer0_kernel(float* __restrict__ emb,
  const int* __restrict__ names, const float* __restrict__ btab,
  const float* __restrict__ bm, const float* __restrict__ bs)
{
  extern __shared__ float smx[];
  float* hA = smx + OFF_HA;
  const int tid=threadIdx.x, cg=tid&31, wid=tid>>5;
  const unsigned smbase = smu32(smx);
  const unsigned barb   = smbase + OFF_BAR*4;
  const int row0 = blockIdx.x*RPB;

  if(tid==0){
    #pragma unroll
    for(int s=0;s<NBUF;s++){ mb_init(barb+s*16, 1); mb_init(barb+s*16+8, 16); }
  }
  for(int i=tid;i<RPB*128;i+=NTHR){
    int r=i>>7, k=i&127;
    float v = btab[names[row0+r]*128 + k];
    hA[i]=v;
    emb[(size_t)(row0+r)*128 + k]=v;
  }
  __syncthreads();

  if(wid==16){
    if(cg==0){
      const float* sched[2]={g_Wmp,g_Wsp};
      producer(barb, smbase, sched, 2);
    }
    return;
  }

  const int team=wid>>2, wsub=wid&3;
  const int d0  = 32*wsub + cg;
  const int tr0 = 4*team;
  int tc = 0;

  u64t acc[4][4];
  zero_acc(acc);
  gemm_pipe(acc, hA, smx, barb, d0, tr0, cg, tc);
  #pragma unroll
  for(int r=0;r<4;r++){
    float* dr = g_EWm + (size_t)(row0+tr0+r)*512;
    #pragma unroll
    for(int g=0;g<4;g++) dr[128*g+d0] = redu(acc[r][g]) + bm[128*g+d0];
  }
  zero_acc(acc);
  gemm_pipe(acc, hA, smx, barb, d0, tr0, cg, tc);
  #pragma unroll
  for(int r=0;r<4;r++){
    float* dr = g_EWs + (size_t)(row0+tr0+r)*512;
    #pragma unroll
    for(int g=0;g<4;g++) dr[128*g+d0] = redu(acc[r][g]) + bs[128*g+d0];
  }
}

// fused pre-shuffle: 4 matrices -> k-pair-packed float2 tables.
// 32768 float2 entries per matrix -> 128 blocks x 256 threads per matrix.
__global__ void shuf_kernel(const float* __restrict__ Um, const float* __restrict__ Us,
                            const float* __restrict__ Wm, const float* __restrict__ Ws)
{
  int b=blockIdx.x, seg=b>>7;
  const float* src = (seg==0)?Um:(seg==1)?Us:(seg==2)?Wm:Ws;
  float* dst = (seg==0)?g_Ump:(seg==1)?g_Usp:(seg==2)?g_Wmp:g_Wsp;
  int i=(b&127)*256+threadIdx.x;         // 0..32767
  int kp=i>>9, col=i&511;
  ((float2*)dst)[i] = make_float2(src[(2*kp)*512+col], src[(2*kp+1)*512+col]);
}

// One-shot constants: z0 = em@Wm + bm -> c0, h0 -> z1b = h0@Um
__global__ void init_kernel(const float* __restrict__ em, const float* __restrict__ Wm,
                            const float* __restrict__ Um, const float* __restrict__ bm)
{
  __shared__ float z0[512]; __shared__ float h0[128]; __shared__ float ems[128];
  int t=threadIdx.x;
  if(t<128) ems[t]=em[t];
  __syncthreads();
  float s=bm[t];
  for(int k=0;k<128;k++) s += ems[k]*Wm[k*512+t];
  z0[t]=s;
  __syncthreads();
  if(t<128){
    float zi=z0[t], zg=z0[256+t], zo=z0[384+t];
    float c = (1.f/(1.f+expf(-zi)))*tanhf(zg);
    g_c0[t]=c;
    h0[t]=(1.f/(1.f+expf(-zo)))*tanhf(c);
  }
  __syncthreads();
  float s2=0.f;
  for(int k=0;k<128;k++) s2 += h0[k]*Um[k*512+t];
  g_z1b[t]=s2;
}

extern "C" void kernel_launch(void* const* d_in, const int* in_sizes, int n_in,
                              void* d_out, int out_size)
{
  const int*   names=(const int*)d_in[0];
  const int*   prop =(const int*)d_in[1];
  const int*   sup  =(const int*)d_in[2];
  const float* btab =(const float*)d_in[3];
  const float* Wm   =(const float*)d_in[4];
  const float* Um   =(const float*)d_in[5];
  const float* bm   =(const float*)d_in[6];
  const float* Ws   =(const float*)d_in[7];
  const float* Us   =(const float*)d_in[8];
  const float* bs   =(const float*)d_in[9];
  const float* em   =(const float*)d_in[10];
  float* emb=(float*)d_out;

  cudaFuncSetAttribute(layer_kernel,  cudaFuncAttributeMaxDynamicSharedMemorySize, SMEMB);
  cudaFuncSetAttribute(layer0_kernel, cudaFuncAttributeMaxDynamicSharedMemorySize, SMEMB);

  init_kernel<<<1,512>>>(em, Wm, Um, bm);
  shuf_kernel<<<512,256>>>(Um, Us, Wm, Ws);
  layer0_kernel<<<NBLK,NTHR,SMEMB>>>(emb, names, btab, bm, bs);
  for(int l=1;l<LLn;l++)
    layer_kernel<<<NBLK,NTHR,SMEMB>>>(l, emb,
        prop + (size_t)l*Mn*Pp, sup + (size_t)l*Mn*Ssn, bm, bs);
}

// round 16
// speedup vs baseline: 1.0580x; 1.0580x over previous
#include <cuda_runtime.h>
#include <cstddef>

#define Mn   2048
#define LLn  64
#define Pp   4
#define Ssn  2
#define RPB  16
#define NTHR 544              /* 16 consumer warps + 1 producer warp */
#define NCONS 512
#define NBLK (Mn/RPB)
#define NBUF 3
#define TILE_FLOATS 16384     /* 32 k x 512 cols x f32 = 64KB */
#define TILE_BYTES  65536

// smem floats: ring 3*16384 | hA 2048 | ids 96 | mbarriers (6 x 16B)
#define OFF_HA  49152
#define OFF_ID  51200
#define OFF_BAR 51296
#define SMEMB   (OFF_BAR*4 + 96)   /* 205280 B */

__device__ __align__(256) float g_EWm[(size_t)LLn * Mn * 512];
__device__ __align__(256) float g_EWs[(size_t)LLn * Mn * 512];
__device__ float g_c0[128];
__device__ float g_z1b[512];
// k-pair packed: [kp(64)][col(512)] float2 = {W[2kp][col], W[2kp+1][col]}
__device__ __align__(256) float g_Ump[65536];
__device__ __align__(256) float g_Usp[65536];
__device__ __align__(256) float g_Wmp[65536];
__device__ __align__(256) float g_Wsp[65536];

typedef unsigned long long u64t;

__device__ __forceinline__ float2 u2f(u64t u){ float2 v; asm("mov.b64 {%0,%1},%2;":"=f"(v.x),"=f"(v.y):"l"(u)); return v; }
__device__ __forceinline__ void fma2(u64t&a, u64t x, u64t w){ asm("fma.rn.f32x2 %0,%1,%2,%0;":"+l"(a):"l"(x),"l"(w)); }
__device__ __forceinline__ float redu(u64t a){ float2 v=u2f(a); return v.x+v.y; }

__device__ __forceinline__ unsigned smu32(const void* p){
  unsigned a; asm("{ .reg .u64 t; cvta.to.shared.u64 t, %1; cvt.u32.u64 %0, t; }":"=r"(a):"l"(p)); return a;
}
__device__ __forceinline__ void mb_init(unsigned mb, unsigned cnt){
  asm volatile("mbarrier.init.shared.b64 [%0], %1;"::"r"(mb),"r"(cnt):"memory");
}
__device__ __forceinline__ void mb_wait(unsigned mb, int ph){
  asm volatile("{\n\t.reg .pred P;\n\tWL%=:\n\tmbarrier.try_wait.parity.acquire.cta.shared::cta.b64 P, [%0], %1, 0x989680;\n\t@P bra WD%=;\n\tbra WL%=;\n\tWD%=:\n\t}"
    ::"r"(mb),"r"(ph):"memory");
}
__device__ __forceinline__ void mb_arrive(unsigned mb){
  asm volatile("mbarrier.arrive.shared.b64 _, [%0];"::"r"(mb):"memory");
}
__device__ __forceinline__ void mb_expect_tx(unsigned mb, unsigned bytes){
  asm volatile("mbarrier.arrive.expect_tx.shared.b64 _, [%0], %1;"::"r"(mb),"r"(bytes):"memory");
}
__device__ __forceinline__ void bulk_cp(unsigned dst, const float* src, unsigned bytes, unsigned mb){
  asm volatile("cp.async.bulk.shared::cta.global.mbarrier::complete_tx::bytes [%0], [%1], %2, [%3];"
    ::"r"(dst),"l"(src),"r"(bytes),"r"(mb):"memory");
}
#define CBAR()  asm volatile("bar.sync 1, %0;"::"n"(NCONS):"memory")
#define TBAR(t) asm volatile("bar.sync %0, 128;"::"r"(2+(t)):"memory")

__device__ __forceinline__ float sigf(float x){ return 1.f/(1.f+__expf(-x)); }
__device__ __forceinline__ float tfast(float x){
  x = fminf(fmaxf(x,-15.f),15.f);
  float t = __expf(2.f*x);
  return (t-1.f)/(t+1.f);
}

// ---------------- producer: stream npass*4 tiles through the 3-ring ----------------
__device__ __forceinline__ void producer(unsigned barb, unsigned smbase,
    const float* const* sched, int npass)
{
  int i=0;
  #pragma unroll 1
  for(int p=0;p<npass;p++){
    const float* W = sched[p];
    #pragma unroll 1
    for(int t=0;t<4;t++,i++){
      int s = i % NBUF;
      unsigned fb = barb + s*16;       // full barrier
      if(i >= NBUF) mb_wait(fb + 8, ((i-NBUF)/NBUF)&1);   // empty barrier
      mb_expect_tx(fb, TILE_BYTES);
      bulk_cp(smbase + s*TILE_BYTES, W + t*TILE_FLOATS, TILE_BYTES, fb);
    }
  }
}

// ---------------- consumer: one 512-col GEMM pass over 4 pipelined 64KB tiles ------
// Thread layout: 16 warps = 4 teams x 4 warps; team=wid>>2 owns rows tr0=4*team..+3.
// Warp wsub=wid&3 covers dims [32*wsub,+32); lane cg owns dim d0=32*wsub+cg.
// Thread's 4 z-cols: gate g -> col 128*g+d0. acc[r][g]: u64 {k-even, k-odd} sums.
// NOTE: gemm reads ONLY its own team's hA rows -> intra-layer sync is per-team.
__device__ __forceinline__ void gemm_pipe(u64t acc[4][4], const float* xs,
    const float* bufbase, unsigned barb, int d0, int tr0, int cg, int& tc)
{
  #pragma unroll 1
  for(int t=0;t<4;t++){
    int s = tc % NBUF;
    unsigned fb = barb + s*16;
    mb_wait(fb, (tc/NBUF)&1);
    const u64t* wb = (const u64t*)(bufbase + s*TILE_FLOATS);
    const float* xb = xs + 32*t;
    #pragma unroll
    for(int kq=0;kq<8;kq++){
      const u64t* wA = wb + (2*kq  )*512 + d0;
      const u64t* wB = wb + (2*kq+1)*512 + d0;
      u64t a0=wA[0], a1=wA[128], a2=wA[256], a3=wA[384];
      u64t b0=wB[0], b1=wB[128], b2=wB[256], b3=wB[384];
      #pragma unroll
      for(int r=0;r<4;r++){
        ulonglong2 xv = *(const ulonglong2*)(xb + (tr0+r)*128 + 4*kq);
        fma2(acc[r][0], xv.x, a0); fma2(acc[r][1], xv.x, a1);
        fma2(acc[r][2], xv.x, a2); fma2(acc[r][3], xv.x, a3);
        fma2(acc[r][0], xv.y, b0); fma2(acc[r][1], xv.y, b1);
        fma2(acc[r][2], xv.y, b2); fma2(acc[r][3], xv.y, b3);
      }
    }
    __syncwarp();
    if(cg==0) mb_arrive(fb + 8);
    tc++;
  }
}

__device__ __forceinline__ void zero_acc(u64t acc[4][4]){
  #pragma unroll
  for(int r=0;r<4;r++)
    #pragma unroll
    for(int g=0;g<4;g++) acc[r][g]=0ull;
}

// z: i,f,g,o scalars for this thread's dim; updates c, returns h.
__device__ __forceinline__ float cell1(const float z[4], float& c){
  c = sigf(z[1])*c + sigf(z[0])*tfast(z[2]);
  return sigf(z[3])*tfast(c);
}

__global__ void __launch_bounds__(NTHR,1) layer_kernel(int l, float* __restrict__ emb,
  const int* __restrict__ prop, const int* __restrict__ sup,
  const float* __restrict__ bm, const float* __restrict__ bs)
{
  extern __shared__ float smx[];
  float* hA  = smx + OFF_HA;
  int*  ids  = (int*)(smx + OFF_ID);
  const int tid=threadIdx.x, cg=tid&31, wid=tid>>5;
  const unsigned smbase = smu32(smx);
  const unsigned barb   = smbase + OFF_BAR*4;
  const int lrow0 = blockIdx.x*RPB;
  const int base  = l*Mn + lrow0;

  if(tid==0){
    #pragma unroll
    for(int s=0;s<NBUF;s++){ mb_init(barb+s*16, 1); mb_init(barb+s*16+8, 16); }
  }
  if(tid<RPB*Pp) ids[tid] = prop[lrow0*Pp + tid];
  else if(tid<RPB*Pp+RPB*Ssn) ids[tid] = sup[lrow0*Ssn + (tid-RPB*Pp)];
  __syncthreads();

  if(wid==16){
    if(cg==0){
      const float* sched[8]={g_Ump,g_Ump,g_Ump,g_Wsp,g_Usp,g_Usp,g_Wmp,g_Wsp};
      producer(barb, smbase, sched, 8);
    }
    return;
  }

  const int team=wid>>2, wsub=wid&3;
  const int d0  = 32*wsub + cg;
  const int tr0 = 4*team;
  int tc = 0;

  u64t acc[4][4];
  float zl[4][4], zz[4][4];
  float cst[4], z[4];

  // ---- member t=1: z = E_Wm[pid0] + z1b ; c_prev = c0
  {
    float c0v = g_c0[d0];
    #pragma unroll
    for(int r=0;r<4;r++){
      const float* e = g_EWm + (size_t)ids[(tr0+r)*Pp]*512;
      #pragma unroll
      for(int g=0;g<4;g++) z[g] = e[128*g+d0] + g_z1b[128*g+d0];
      cst[r]=c0v;
      hA[(tr0+r)*128 + d0] = cell1(z, cst[r]);
    }
  }
  TBAR(team);

  // ---- member t=2..4: z = E_Wm[pid_{t-1}] + h @ Um
  #pragma unroll 1
  for(int t=2;t<=4;t++){
    zero_acc(acc);
    gemm_pipe(acc, hA, smx, barb, d0, tr0, cg, tc);
    #pragma unroll
    for(int r=0;r<4;r++){
      const float* e = g_EWm + (size_t)ids[(tr0+r)*Pp + (t-1)]*512;
      #pragma unroll
      for(int g=0;g<4;g++) zz[r][g] = redu(acc[r][g]) + e[128*g+d0];
    }
    TBAR(team);                   // team done reading its hA rows
    #pragma unroll
    for(int r=0;r<4;r++) hA[(tr0+r)*128 + d0] = cell1(zz[r], cst[r]);
    TBAR(team);                   // new h visible to team
  }
  // hA == h_m

  // ---- zl = b_s + h_m @ Ws  (x-contribution of super t=2, kept in regs)
  zero_acc(acc);
  gemm_pipe(acc, hA, smx, barb, d0, tr0, cg, tc);
  #pragma unroll
  for(int r=0;r<4;r++)
    #pragma unroll
    for(int g=0;g<4;g++) zl[r][g] = redu(acc[r][g]) + bs[128*g+d0];
  TBAR(team);                     // team done reading h_m

  // ---- super t=0: z = E_Ws[sid0], zero state
  #pragma unroll
  for(int r=0;r<4;r++){
    const float* e = g_EWs + (size_t)ids[RPB*Pp + (tr0+r)*Ssn]*512;
    #pragma unroll
    for(int g=0;g<4;g++) z[g] = e[128*g+d0];
    cst[r]=0.f;
    hA[(tr0+r)*128 + d0] = cell1(z, cst[r]);
  }
  TBAR(team);

  // ---- super t=1: z = E_Ws[sid1] + h @ Us
  zero_acc(acc);
  gemm_pipe(acc, hA, smx, barb, d0, tr0, cg, tc);
  #pragma unroll
  for(int r=0;r<4;r++){
    const float* e = g_EWs + (size_t)ids[RPB*Pp + (tr0+r)*Ssn + 1]*512;
    #pragma unroll
    for(int g=0;g<4;g++) zz[r][g] = redu(acc[r][g]) + e[128*g+d0];
  }
  TBAR(team);
  #pragma unroll
  for(int r=0;r<4;r++) hA[(tr0+r)*128 + d0] = cell1(zz[r], cst[r]);
  TBAR(team);

  // ---- super t=2: z = zl + h @ Us -> h_s
  zero_acc(acc);
  gemm_pipe(acc, hA, smx, barb, d0, tr0, cg, tc);
  #pragma unroll
  for(int r=0;r<4;r++)
    #pragma unroll
    for(int g=0;g<4;g++) zz[r][g] = redu(acc[r][g]) + zl[r][g];
  TBAR(team);
  #pragma unroll
  for(int r=0;r<4;r++) hA[(tr0+r)*128 + d0] = cell1(zz[r], cst[r]);

  // ---- write emb rows (cross-team read of hA -> one full consumer barrier)
  CBAR();
  ((float4*)(emb + (size_t)base*128))[tid] = ((const float4*)hA)[tid];

  // ---- produce z-tables for this layer's rows (gemm reads own-team hA rows only)
  zero_acc(acc);
  gemm_pipe(acc, hA, smx, barb, d0, tr0, cg, tc);
  #pragma unroll
  for(int r=0;r<4;r++){
    float* dr = g_EWm + (size_t)(base+tr0+r)*512;
    #pragma unroll
    for(int g=0;g<4;g++) dr[128*g+d0] = redu(acc[r][g]) + bm[128*g+d0];
  }
  zero_acc(acc);
  gemm_pipe(acc, hA, smx, barb, d0, tr0, cg, tc);
  #pragma unroll
  for(int r=0;r<4;r++){
    float* dr = g_EWs + (size_t)(base+tr0+r)*512;
    #pragma unroll
    for(int g=0;g<4;g++) dr[128*g+d0] = redu(acc[r][g]) + bs[128*g+d0];
  }
}

__global__ void __launch_bounds__(NTHR,1) layer0_kernel(float* __restrict__ emb,
  const int* __restrict__ names, const float* __restrict__ btab,
  const float* __restrict__ bm, const float* __restrict__ bs)
{
  extern __shared__ float smx[];
  float* hA = smx + OFF_HA;
  const int tid=threadIdx.x, cg=tid&31, wid=tid>>5;
  const unsigned smbase = smu32(smx);
  const unsigned barb   = smbase + OFF_BAR*4;
  const int row0 = blockIdx.x*RPB;

  if(tid==0){
    #pragma unroll
    for(int s=0;s<NBUF;s++){ mb_init(barb+s*16, 1); mb_init(barb+s*16+8, 16); }
  }
  for(int i=tid;i<RPB*128;i+=NTHR){
    int r=i>>7, k=i&127;
    float v = btab[names[row0+r]*128 + k];
    hA[i]=v;
    emb[(size_t)(row0+r)*128 + k]=v;
  }
  __syncthreads();

  if(wid==16){
    if(cg==0){
      const float* sched[2]={g_Wmp,g_Wsp};
      producer(barb, smbase, sched, 2);
    }
    return;
  }

  const int team=wid>>2, wsub=wid&3;
  const int d0  = 32*wsub + cg;
  const int tr0 = 4*team;
  int tc = 0;

  u64t acc[4][4];
  zero_acc(acc);
  gemm_pipe(acc, hA, smx, barb, d0, tr0, cg, tc);
  #pragma unroll
  for(int r=0;r<4;r++){
    float* dr = g_EWm + (size_t)(row0+tr0+r)*512;
    #pragma unroll
    for(int g=0;g<4;g++) dr[128*g+d0] = redu(acc[r][g]) + bm[128*g+d0];
  }
  zero_acc(acc);
  gemm_pipe(acc, hA, smx, barb, d0, tr0, cg, tc);
  #pragma unroll
  for(int r=0;r<4;r++){
    float* dr = g_EWs + (size_t)(row0+tr0+r)*512;
    #pragma unroll
    for(int g=0;g<4;g++) dr[128*g+d0] = redu(acc[r][g]) + bs[128*g+d0];
  }
}

// fused pre-shuffle: 4 matrices -> k-pair-packed float2 tables.
// 32768 float2 entries per matrix -> 128 blocks x 256 threads per matrix.
__global__ void shuf_kernel(const float* __restrict__ Um, const float* __restrict__ Us,
                            const float* __restrict__ Wm, const float* __restrict__ Ws)
{
  int b=blockIdx.x, seg=b>>7;
  const float* src = (seg==0)?Um:(seg==1)?Us:(seg==2)?Wm:Ws;
  float* dst = (seg==0)?g_Ump:(seg==1)?g_Usp:(seg==2)?g_Wmp:g_Wsp;
  int i=(b&127)*256+threadIdx.x;         // 0..32767
  int kp=i>>9, col=i&511;
  ((float2*)dst)[i] = make_float2(src[(2*kp)*512+col], src[(2*kp+1)*512+col]);
}

// One-shot constants: z0 = em@Wm + bm -> c0, h0 -> z1b = h0@Um
__global__ void init_kernel(const float* __restrict__ em, const float* __restrict__ Wm,
                            const float* __restrict__ Um, const float* __restrict__ bm)
{
  __shared__ float z0[512]; __shared__ float h0[128]; __shared__ float ems[128];
  int t=threadIdx.x;
  if(t<128) ems[t]=em[t];
  __syncthreads();
  float s=bm[t];
  for(int k=0;k<128;k++) s += ems[k]*Wm[k*512+t];
  z0[t]=s;
  __syncthreads();
  if(t<128){
    float zi=z0[t], zg=z0[256+t], zo=z0[384+t];
    float c = (1.f/(1.f+expf(-zi)))*tanhf(zg);
    g_c0[t]=c;
    h0[t]=(1.f/(1.f+expf(-zo)))*tanhf(c);
  }
  __syncthreads();
  float s2=0.f;
  for(int k=0;k<128;k++) s2 += h0[k]*Um[k*512+t];
  g_z1b[t]=s2;
}

extern "C" void kernel_launch(void* const* d_in, const int* in_sizes, int n_in,
                              void* d_out, int out_size)
{
  const int*   names=(const int*)d_in[0];
  const int*   prop =(const int*)d_in[1];
  const int*   sup  =(const int*)d_in[2];
  const float* btab =(const float*)d_in[3];
  const float* Wm   =(const float*)d_in[4];
  const float* Um   =(const float*)d_in[5];
  const float* bm   =(const float*)d_in[6];
  const float* Ws   =(const float*)d_in[7];
  const float* Us   =(const float*)d_in[8];
  const float* bs   =(const float*)d_in[9];
  const float* em   =(const float*)d_in[10];
  float* emb=(float*)d_out;

  cudaFuncSetAttribute(layer_kernel,  cudaFuncAttributeMaxDynamicSharedMemorySize, SMEMB);
  cudaFuncSetAttribute(layer0_kernel, cudaFuncAttributeMaxDynamicSharedMemorySize, SMEMB);

  init_kernel<<<1,512>>>(em, Wm, Um, bm);
  shuf_kernel<<<512,256>>>(Um, Us, Wm, Ws);
  layer0_kernel<<<NBLK,NTHR,SMEMB>>>(emb, names, btab, bm, bs);
  for(int l=1;l<LLn;l++)
    layer_kernel<<<NBLK,NTHR,SMEMB>>>(l, emb,
        prop + (size_t)l*Mn*Pp, sup + (size_t)l*Mn*Ssn, bm, bs);
}